// round 1
// baseline (speedup 1.0000x reference)
#include <cuda_runtime.h>
#include <math.h>

#define BB 4
#define SS 2048
#define DD 1024

// Scratch (allocation-free rule: __device__ globals)
__device__ float g_q[BB * SS * DD];          // 33.5 MB
__device__ float g_k[BB * SS * DD];
__device__ float g_v[BB * SS * DD];
__device__ float g_p[(size_t)BB * SS * SS];  // 67 MB  (scores -> probs)

// ---------------------------------------------------------------------------
// Kernel 1: fused QKV projection.  C[m,n] = sum_k x[m,k] * W[n,k]
// Both A and W are K-major (row-major [rows, 1024]) -> "NT" sgemm.
// 128x128 block tile, TK=16, 256 threads, 8x8 per-thread microtile.
// grid = (N/128, M/128, 3)  z selects (Wq->g_q, Wk->g_k, Wv->g_v)
// ---------------------------------------------------------------------------
__global__ __launch_bounds__(256) void qkv_gemm(
    const float* __restrict__ x,
    const float* __restrict__ wq,
    const float* __restrict__ wk,
    const float* __restrict__ wv)
{
    const float* W = (blockIdx.z == 0) ? wq : (blockIdx.z == 1) ? wk : wv;
    float* C = (blockIdx.z == 0) ? g_q : (blockIdx.z == 1) ? g_k : g_v;

    const int m0 = blockIdx.y * 128;
    const int n0 = blockIdx.x * 128;

    __shared__ float As[16][128];
    __shared__ float Bs[16][128];

    float acc[8][8];
#pragma unroll
    for (int i = 0; i < 8; i++)
#pragma unroll
        for (int j = 0; j < 8; j++) acc[i][j] = 0.0f;

    const int tid = threadIdx.x;
    const int tx = tid & 15;
    const int ty = tid >> 4;

    for (int k0 = 0; k0 < DD; k0 += 16) {
#pragma unroll
        for (int l = 0; l < 2; l++) {
            int s = tid * 2 + l;            // 0..511
            int row = s >> 2;               // 0..127
            int kc = (s & 3) * 4;           // 0,4,8,12
            float4 va = *(const float4*)&x[(size_t)(m0 + row) * DD + k0 + kc];
            As[kc + 0][row] = va.x; As[kc + 1][row] = va.y;
            As[kc + 2][row] = va.z; As[kc + 3][row] = va.w;
            float4 vb = *(const float4*)&W[(size_t)(n0 + row) * DD + k0 + kc];
            Bs[kc + 0][row] = vb.x; Bs[kc + 1][row] = vb.y;
            Bs[kc + 2][row] = vb.z; Bs[kc + 3][row] = vb.w;
        }
        __syncthreads();
#pragma unroll
        for (int k = 0; k < 16; k++) {
            float a[8], b[8];
#pragma unroll
            for (int i = 0; i < 8; i++) a[i] = As[k][ty * 8 + i];
#pragma unroll
            for (int j = 0; j < 8; j++) b[j] = Bs[k][tx * 8 + j];
#pragma unroll
            for (int i = 0; i < 8; i++)
#pragma unroll
                for (int j = 0; j < 8; j++) acc[i][j] += a[i] * b[j];
        }
        __syncthreads();
    }

#pragma unroll
    for (int i = 0; i < 8; i++)
#pragma unroll
        for (int j = 0; j < 8; j++)
            C[(size_t)(m0 + ty * 8 + i) * DD + n0 + tx * 8 + j] = acc[i][j];
}

// ---------------------------------------------------------------------------
// Kernel 2: causal scores.  P[b,i,j] = (1/32) * dot(Q[b,i,:], K[b,j,:])
// Only lower-triangular 128x128 tiles (jt <= it): 136 tiles per batch.
// grid = (136, B)
// ---------------------------------------------------------------------------
__global__ __launch_bounds__(256) void scores_gemm()
{
    const int t = blockIdx.x;
    // decode triangular index: it such that it*(it+1)/2 <= t < (it+1)*(it+2)/2
    int it = (int)floorf((sqrtf(8.0f * (float)t + 1.0f) - 1.0f) * 0.5f);
    while ((it + 1) * (it + 2) / 2 <= t) ++it;
    while (it * (it + 1) / 2 > t) --it;
    const int jt = t - it * (it + 1) / 2;

    const int b = blockIdx.y;
    const int m0 = it * 128;
    const int n0 = jt * 128;

    const float* A = &g_q[(size_t)b * SS * DD];
    const float* Bk = &g_k[(size_t)b * SS * DD];
    float* C = &g_p[(size_t)b * SS * SS];

    __shared__ float As[16][128];
    __shared__ float Bs[16][128];

    float acc[8][8];
#pragma unroll
    for (int i = 0; i < 8; i++)
#pragma unroll
        for (int j = 0; j < 8; j++) acc[i][j] = 0.0f;

    const int tid = threadIdx.x;
    const int tx = tid & 15;
    const int ty = tid >> 4;

    for (int k0 = 0; k0 < DD; k0 += 16) {
#pragma unroll
        for (int l = 0; l < 2; l++) {
            int s = tid * 2 + l;
            int row = s >> 2;
            int kc = (s & 3) * 4;
            float4 va = *(const float4*)&A[(size_t)(m0 + row) * DD + k0 + kc];
            As[kc + 0][row] = va.x; As[kc + 1][row] = va.y;
            As[kc + 2][row] = va.z; As[kc + 3][row] = va.w;
            float4 vb = *(const float4*)&Bk[(size_t)(n0 + row) * DD + k0 + kc];
            Bs[kc + 0][row] = vb.x; Bs[kc + 1][row] = vb.y;
            Bs[kc + 2][row] = vb.z; Bs[kc + 3][row] = vb.w;
        }
        __syncthreads();
#pragma unroll
        for (int k = 0; k < 16; k++) {
            float a[8], b2[8];
#pragma unroll
            for (int i = 0; i < 8; i++) a[i] = As[k][ty * 8 + i];
#pragma unroll
            for (int j = 0; j < 8; j++) b2[j] = Bs[k][tx * 8 + j];
#pragma unroll
            for (int i = 0; i < 8; i++)
#pragma unroll
                for (int j = 0; j < 8; j++) acc[i][j] += a[i] * b2[j];
        }
        __syncthreads();
    }

    const float alpha = 1.0f / 32.0f;  // 1/sqrt(1024)
#pragma unroll
    for (int i = 0; i < 8; i++)
#pragma unroll
        for (int j = 0; j < 8; j++)
            C[(size_t)(m0 + ty * 8 + i) * SS + n0 + tx * 8 + j] = acc[i][j] * alpha;
}

// ---------------------------------------------------------------------------
// Kernel 3: causal row softmax over P, in place.
// One block of 256 threads per row.  Also zero-fills the j in (i, tile_end)
// region so the PV gemm needs no mask.
// grid = (S, B)
// ---------------------------------------------------------------------------
__global__ __launch_bounds__(256) void softmax_rows()
{
    const int i = blockIdx.x;
    const int b = blockIdx.y;
    float* row = &g_p[((size_t)b * SS + i) * SS];
    const int len = i + 1;
    const int tid = threadIdx.x;
    const int lane = tid & 31;
    const int wid = tid >> 5;

    __shared__ float red[8];
    __shared__ float s_max, s_sum;

    // pass 1: max
    float m = -1e30f;
    for (int j = tid; j < len; j += 256) m = fmaxf(m, row[j]);
#pragma unroll
    for (int o = 16; o; o >>= 1) m = fmaxf(m, __shfl_xor_sync(0xffffffffu, m, o));
    if (lane == 0) red[wid] = m;
    __syncthreads();
    if (tid < 32) {
        float v = (tid < 8) ? red[tid] : -1e30f;
#pragma unroll
        for (int o = 4; o; o >>= 1) v = fmaxf(v, __shfl_xor_sync(0xffffffffu, v, o));
        if (tid == 0) s_max = v;
    }
    __syncthreads();
    m = s_max;

    // pass 2: exp + sum
    float s = 0.0f;
    for (int j = tid; j < len; j += 256) {
        float e = __expf(row[j] - m);
        row[j] = e;
        s += e;
    }
#pragma unroll
    for (int o = 16; o; o >>= 1) s += __shfl_xor_sync(0xffffffffu, s, o);
    __syncthreads();   // red[] reuse
    if (lane == 0) red[wid] = s;
    __syncthreads();
    if (tid < 32) {
        float v = (tid < 8) ? red[tid] : 0.0f;
#pragma unroll
        for (int o = 4; o; o >>= 1) v += __shfl_xor_sync(0xffffffffu, v, o);
        if (tid == 0) s_sum = v;
    }
    __syncthreads();
    const float inv = 1.0f / s_sum;

    // pass 3: normalize + zero-fill up to the 128-tile boundary
    for (int j = tid; j < len; j += 256) row[j] *= inv;
    const int tend = ((i >> 7) + 1) << 7;  // ceil to 128-tile
    for (int j = len + tid; j < tend; j += 256) row[j] = 0.0f;
}

// ---------------------------------------------------------------------------
// Kernel 4: O = P @ V.  A = P [S,S] (k contiguous), B = V [S,D] (n contiguous).
// Causal: row tile it only needs k < (it+1)*128.
// grid = (D/128, S/128, B)
// ---------------------------------------------------------------------------
__global__ __launch_bounds__(256) void pv_gemm(float* __restrict__ out)
{
    const int b = blockIdx.z;
    const int m0 = blockIdx.y * 128;
    const int n0 = blockIdx.x * 128;
    const int kend = (blockIdx.y + 1) * 128;

    const float* A = &g_p[(size_t)b * SS * SS];
    const float* Bv = &g_v[(size_t)b * SS * DD];
    float* C = out + (size_t)b * SS * DD;

    __shared__ float As[16][128];
    __shared__ float Bs[16][128];

    float acc[8][8];
#pragma unroll
    for (int i = 0; i < 8; i++)
#pragma unroll
        for (int j = 0; j < 8; j++) acc[i][j] = 0.0f;

    const int tid = threadIdx.x;
    const int tx = tid & 15;
    const int ty = tid >> 4;

    for (int k0 = 0; k0 < kend; k0 += 16) {
#pragma unroll
        for (int l = 0; l < 2; l++) {
            int s = tid * 2 + l;
            // A: 128 rows x 16 k, transpose into As[k][m]
            int row = s >> 2;
            int kc = (s & 3) * 4;
            float4 va = *(const float4*)&A[(size_t)(m0 + row) * SS + k0 + kc];
            As[kc + 0][row] = va.x; As[kc + 1][row] = va.y;
            As[kc + 2][row] = va.z; As[kc + 3][row] = va.w;
            // B: 16 k-rows x 128 n, direct copy into Bs[k][n]
            int kr = s >> 5;          // 0..15
            int nc = (s & 31) * 4;    // 0..124
            float4 vb = *(const float4*)&Bv[(size_t)(k0 + kr) * DD + n0 + nc];
            *(float4*)&Bs[kr][nc] = vb;
        }
        __syncthreads();
#pragma unroll
        for (int k = 0; k < 16; k++) {
            float a[8], v[8];
#pragma unroll
            for (int i = 0; i < 8; i++) a[i] = As[k][ty * 8 + i];
#pragma unroll
            for (int j = 0; j < 8; j++) v[j] = Bs[k][tx * 8 + j];
#pragma unroll
            for (int i = 0; i < 8; i++)
#pragma unroll
                for (int j = 0; j < 8; j++) acc[i][j] += a[i] * v[j];
        }
        __syncthreads();
    }

#pragma unroll
    for (int i = 0; i < 8; i++)
#pragma unroll
        for (int j = 0; j < 8; j++)
            C[(size_t)(m0 + ty * 8 + i) * DD + n0 + tx * 8 + j] = acc[i][j];
}

// ---------------------------------------------------------------------------
extern "C" void kernel_launch(void* const* d_in, const int* in_sizes, int n_in,
                              void* d_out, int out_size)
{
    const float* x  = (const float*)d_in[0];
    const float* wq = (const float*)d_in[1];
    const float* wk = (const float*)d_in[2];
    const float* wv = (const float*)d_in[3];
    float* out = (float*)d_out;

    (void)in_sizes; (void)n_in; (void)out_size;

    // 1) Q, K, V projections
    dim3 g1(DD / 128, (BB * SS) / 128, 3);   // (8, 64, 3)
    qkv_gemm<<<g1, 256>>>(x, wq, wk, wv);

    // 2) causal scores (lower-triangular tiles only)
    const int ntri = (SS / 128) * (SS / 128 + 1) / 2;  // 136
    scores_gemm<<<dim3(ntri, BB), 256>>>();

    // 3) softmax per row
    softmax_rows<<<dim3(SS, BB), 256>>>();

    // 4) O = P @ V
    pv_gemm<<<dim3(DD / 128, SS / 128, BB), 256>>>(out);
}

// round 3
// speedup vs baseline: 2.3019x; 2.3019x over previous
#include <cuda_runtime.h>
#include <cuda_bf16.h>
#include <cstdint>
#include <math.h>

#define BB 4
#define SS 2048
#define DD 1024
#define LDW 20          // padded SMEM row stride in 32-bit words (16 data + 4 pad)

// ---------------------------------------------------------------------------
// Scratch (__device__ globals; allocation-free rule)
// ---------------------------------------------------------------------------
__device__ __align__(16) __nv_bfloat16 g_x_hi[BB*SS*DD], g_x_lo[BB*SS*DD];
__device__ __align__(16) __nv_bfloat16 g_w_hi[3][DD*DD], g_w_lo[3][DD*DD];
__device__ __align__(16) __nv_bfloat16 g_q_hi[BB*SS*DD], g_q_lo[BB*SS*DD];
__device__ __align__(16) __nv_bfloat16 g_k_hi[BB*SS*DD], g_k_lo[BB*SS*DD];
__device__ __align__(16) __nv_bfloat16 g_vT_hi[BB*DD*SS], g_vT_lo[BB*DD*SS];  // [b][d][s]
__device__ __align__(16) float g_p[(size_t)BB*SS*SS];
__device__ __align__(16) __nv_bfloat16 g_p_hi[BB*SS*SS], g_p_lo[BB*SS*SS];

// ---------------------------------------------------------------------------
// mma.sync m16n8k16 bf16 (sm_80+ path; no 'a'-feature needed)
// ---------------------------------------------------------------------------
__device__ __forceinline__ void mma_bf16(float* d, const uint32_t* a, const uint32_t* b) {
    asm volatile(
        "mma.sync.aligned.m16n8k16.row.col.f32.bf16.bf16.f32 "
        "{%0,%1,%2,%3}, {%4,%5,%6,%7}, {%8,%9}, {%0,%1,%2,%3};"
        : "+f"(d[0]), "+f"(d[1]), "+f"(d[2]), "+f"(d[3])
        : "r"(a[0]), "r"(a[1]), "r"(a[2]), "r"(a[3]), "r"(b[0]), "r"(b[1]));
}

struct SmemTiles {
    uint32_t Ah[128 * LDW];
    uint32_t Al[128 * LDW];
    uint32_t Bh[128 * LDW];
    uint32_t Bl[128 * LDW];
};

// load 128 rows x 32 bf16 from global (K-major, row stride ld elems) into padded smem
__device__ __forceinline__ void g2s_tile(const __nv_bfloat16* __restrict__ g,
                                         size_t ld, int k0, uint32_t* dst, int tid) {
#pragma unroll
    for (int i = 0; i < 2; i++) {
        int slot = tid + (i << 8);          // 0..511
        int row = slot >> 2;                // 0..127
        int c8 = slot & 3;                  // 8-bf16 block
        float4 v = *(const float4*)(g + (size_t)row * ld + k0 + c8 * 8);
        *(float4*)&dst[row * LDW + c8 * 4] = v;
    }
}

// ---------------------------------------------------------------------------
// Shared mainloop: acc[4][4][4] += split3(A[128,K]) . split3(B[128,K])^T
// ---------------------------------------------------------------------------
__device__ __forceinline__ void mma_mainloop(
    const __nv_bfloat16* Ah, const __nv_bfloat16* Al,
    const __nv_bfloat16* Bh, const __nv_bfloat16* Bl,
    size_t lda, size_t ldb, int nch, SmemTiles* sm, float acc[4][4][4]) {

    const int tid = threadIdx.x;
    const int lane = tid & 31, wid = tid >> 5;
    const int wm = wid >> 2, wn = wid & 3;
    const int g = lane >> 2, tg = lane & 3;
    const int am = wm * 64, bn = wn * 32;

    for (int c = 0; c < nch; c++) {
        const int k0 = c * 32;
        g2s_tile(Ah, lda, k0, sm->Ah, tid);
        g2s_tile(Al, lda, k0, sm->Al, tid);
        g2s_tile(Bh, ldb, k0, sm->Bh, tid);
        g2s_tile(Bl, ldb, k0, sm->Bl, tid);
        __syncthreads();

#pragma unroll
        for (int ks = 0; ks < 2; ks++) {
            const int kw = ks * 8;
            uint32_t ah[4][4], bh[4][2], bl[4][2];
#pragma unroll
            for (int fm = 0; fm < 4; fm++) {
                int base = (am + fm * 16 + g) * LDW + kw + tg;
                ah[fm][0] = sm->Ah[base];
                ah[fm][1] = sm->Ah[base + 8 * LDW];
                ah[fm][2] = sm->Ah[base + 4];
                ah[fm][3] = sm->Ah[base + 8 * LDW + 4];
            }
#pragma unroll
            for (int fn = 0; fn < 4; fn++) {
                int base = (bn + fn * 8 + g) * LDW + kw + tg;
                bh[fn][0] = sm->Bh[base];
                bh[fn][1] = sm->Bh[base + 4];
                bl[fn][0] = sm->Bl[base];
                bl[fn][1] = sm->Bl[base + 4];
            }
            // term 1: Ah x Bh
#pragma unroll
            for (int fm = 0; fm < 4; fm++)
#pragma unroll
                for (int fn = 0; fn < 4; fn++) mma_bf16(acc[fm][fn], ah[fm], bh[fn]);
            // term 2: Ah x Bl
#pragma unroll
            for (int fm = 0; fm < 4; fm++)
#pragma unroll
                for (int fn = 0; fn < 4; fn++) mma_bf16(acc[fm][fn], ah[fm], bl[fn]);
            // term 3: Al x Bh  (reuse ah regs)
#pragma unroll
            for (int fm = 0; fm < 4; fm++) {
                int base = (am + fm * 16 + g) * LDW + kw + tg;
                ah[fm][0] = sm->Al[base];
                ah[fm][1] = sm->Al[base + 8 * LDW];
                ah[fm][2] = sm->Al[base + 4];
                ah[fm][3] = sm->Al[base + 8 * LDW + 4];
            }
#pragma unroll
            for (int fm = 0; fm < 4; fm++)
#pragma unroll
                for (int fn = 0; fn < 4; fn++) mma_bf16(acc[fm][fn], ah[fm], bh[fn]);
        }
        __syncthreads();
    }
}

// ---------------------------------------------------------------------------
// Kernel 0: split fp32 -> (hi, lo) bf16 for x, Wq, Wk, Wv
// ---------------------------------------------------------------------------
__global__ __launch_bounds__(256) void split_all(
    const float* __restrict__ x, const float* __restrict__ wq,
    const float* __restrict__ wk, const float* __restrict__ wv) {
    const int which = blockIdx.y;
    const float* src = (which == 0) ? x : (which == 1) ? wq : (which == 2) ? wk : wv;
    __nv_bfloat16* hi = (which == 0) ? g_x_hi : g_w_hi[which - 1];
    __nv_bfloat16* lo = (which == 0) ? g_x_lo : g_w_lo[which - 1];
    const int n = (which == 0) ? BB * SS * DD : DD * DD;
    for (int i = blockIdx.x * 256 + threadIdx.x; i < n; i += gridDim.x * 256) {
        float f = src[i];
        __nv_bfloat16 h = __float2bfloat16(f);
        hi[i] = h;
        lo[i] = __float2bfloat16(f - __bfloat162float(h));
    }
}

// ---------------------------------------------------------------------------
// Kernel 1: QKV.  z=0 -> Q(split), z=1 -> K(split), z=2 -> V^T(split)
// ---------------------------------------------------------------------------
__global__ __launch_bounds__(256, 2) void qkv_mma() {
    __shared__ SmemTiles sm;
    const int z = blockIdx.z;
    const int m0 = blockIdx.y * 128;
    const int n0 = blockIdx.x * 128;

    float acc[4][4][4];
#pragma unroll
    for (int i = 0; i < 4; i++)
#pragma unroll
        for (int j = 0; j < 4; j++)
#pragma unroll
            for (int r = 0; r < 4; r++) acc[i][j][r] = 0.0f;

    mma_mainloop(g_x_hi + (size_t)m0 * DD, g_x_lo + (size_t)m0 * DD,
                 g_w_hi[z] + (size_t)n0 * DD, g_w_lo[z] + (size_t)n0 * DD,
                 DD, DD, DD / 32, &sm, acc);

    const int lane = threadIdx.x & 31, wid = threadIdx.x >> 5;
    const int wm = wid >> 2, wn = wid & 3;
    const int g = lane >> 2, tg = lane & 3;

#pragma unroll
    for (int fm = 0; fm < 4; fm++) {
#pragma unroll
        for (int fn = 0; fn < 4; fn++) {
            const int n = n0 + wn * 32 + fn * 8 + tg * 2;
#pragma unroll
            for (int half = 0; half < 2; half++) {
                const int m = m0 + wm * 64 + fm * 16 + g + half * 8;
                float f0 = acc[fm][fn][half * 2], f1 = acc[fm][fn][half * 2 + 1];
                if (z < 2) {
                    __nv_bfloat16* H = z ? g_k_hi : g_q_hi;
                    __nv_bfloat16* L = z ? g_k_lo : g_q_lo;
                    __nv_bfloat16 h0 = __float2bfloat16(f0), h1 = __float2bfloat16(f1);
                    __nv_bfloat162 h2; h2.x = h0; h2.y = h1;
                    __nv_bfloat162 l2;
                    l2.x = __float2bfloat16(f0 - __bfloat162float(h0));
                    l2.y = __float2bfloat16(f1 - __bfloat162float(h1));
                    *(__nv_bfloat162*)(H + (size_t)m * DD + n) = h2;
                    *(__nv_bfloat162*)(L + (size_t)m * DD + n) = l2;
                } else {
                    const int b = m >> 11, ml = m & (SS - 1);
                    const size_t vb = (size_t)b * DD * SS;
                    __nv_bfloat16 h0 = __float2bfloat16(f0), h1 = __float2bfloat16(f1);
                    g_vT_hi[vb + (size_t)n * SS + ml] = h0;
                    g_vT_lo[vb + (size_t)n * SS + ml] = __float2bfloat16(f0 - __bfloat162float(h0));
                    g_vT_hi[vb + (size_t)(n + 1) * SS + ml] = h1;
                    g_vT_lo[vb + (size_t)(n + 1) * SS + ml] = __float2bfloat16(f1 - __bfloat162float(h1));
                }
            }
        }
    }
}

// ---------------------------------------------------------------------------
// Kernel 2: causal scores (lower-triangular 128x128 tiles)
// ---------------------------------------------------------------------------
__global__ __launch_bounds__(256, 2) void scores_mma() {
    __shared__ SmemTiles sm;
    const int t = blockIdx.x;
    int it = (int)floorf((sqrtf(8.0f * (float)t + 1.0f) - 1.0f) * 0.5f);
    while ((it + 1) * (it + 2) / 2 <= t) ++it;
    while (it * (it + 1) / 2 > t) --it;
    const int jt = t - it * (it + 1) / 2;
    const int b = blockIdx.y;
    const int m0 = it * 128, n0 = jt * 128;

    float acc[4][4][4];
#pragma unroll
    for (int i = 0; i < 4; i++)
#pragma unroll
        for (int j = 0; j < 4; j++)
#pragma unroll
            for (int r = 0; r < 4; r++) acc[i][j][r] = 0.0f;

    const size_t ao = ((size_t)b * SS + m0) * DD;
    const size_t bo = ((size_t)b * SS + n0) * DD;
    mma_mainloop(g_q_hi + ao, g_q_lo + ao, g_k_hi + bo, g_k_lo + bo,
                 DD, DD, DD / 32, &sm, acc);

    const int lane = threadIdx.x & 31, wid = threadIdx.x >> 5;
    const int wm = wid >> 2, wn = wid & 3;
    const int g = lane >> 2, tg = lane & 3;
    float* C = g_p + (size_t)b * SS * SS;
    const float alpha = 1.0f / 32.0f;

#pragma unroll
    for (int fm = 0; fm < 4; fm++)
#pragma unroll
        for (int fn = 0; fn < 4; fn++) {
            const int n = n0 + wn * 32 + fn * 8 + tg * 2;
#pragma unroll
            for (int half = 0; half < 2; half++) {
                const int m = m0 + wm * 64 + fm * 16 + g + half * 8;
                float2 v;
                v.x = acc[fm][fn][half * 2] * alpha;
                v.y = acc[fm][fn][half * 2 + 1] * alpha;
                *(float2*)(C + (size_t)m * SS + n) = v;
            }
        }
}

// ---------------------------------------------------------------------------
// Kernel 3: causal row softmax; emits split-bf16 P, zero-filled to tile edge
// ---------------------------------------------------------------------------
__global__ __launch_bounds__(256) void softmax_rows() {
    const int i = blockIdx.x, b = blockIdx.y;
    const size_t rowoff = ((size_t)b * SS + i) * SS;
    float* row = g_p + rowoff;
    const int len = i + 1;
    const int tid = threadIdx.x, lane = tid & 31, wid = tid >> 5;

    __shared__ float red[8];
    __shared__ float s_max, s_sum;

    float m = -1e30f;
    for (int j = tid; j < len; j += 256) m = fmaxf(m, row[j]);
#pragma unroll
    for (int o = 16; o; o >>= 1) m = fmaxf(m, __shfl_xor_sync(0xffffffffu, m, o));
    if (lane == 0) red[wid] = m;
    __syncthreads();
    if (tid < 32) {
        float v = (tid < 8) ? red[tid] : -1e30f;
#pragma unroll
        for (int o = 4; o; o >>= 1) v = fmaxf(v, __shfl_xor_sync(0xffffffffu, v, o));
        if (tid == 0) s_max = v;
    }
    __syncthreads();
    m = s_max;

    float s = 0.0f;
    for (int j = tid; j < len; j += 256) {
        float e = __expf(row[j] - m);
        row[j] = e;
        s += e;
    }
#pragma unroll
    for (int o = 16; o; o >>= 1) s += __shfl_xor_sync(0xffffffffu, s, o);
    __syncthreads();
    if (lane == 0) red[wid] = s;
    __syncthreads();
    if (tid < 32) {
        float v = (tid < 8) ? red[tid] : 0.0f;
#pragma unroll
        for (int o = 4; o; o >>= 1) v += __shfl_xor_sync(0xffffffffu, v, o);
        if (tid == 0) s_sum = v;
    }
    __syncthreads();
    const float inv = 1.0f / s_sum;

    __nv_bfloat16* ph = g_p_hi + rowoff;
    __nv_bfloat16* pl = g_p_lo + rowoff;
    for (int j = tid; j < len; j += 256) {
        float p = row[j] * inv;
        __nv_bfloat16 h = __float2bfloat16(p);
        ph[j] = h;
        pl[j] = __float2bfloat16(p - __bfloat162float(h));
    }
    const int tend = ((i >> 7) + 1) << 7;
    const __nv_bfloat16 z = __float2bfloat16(0.0f);
    for (int j = len + tid; j < tend; j += 256) { ph[j] = z; pl[j] = z; }
}

// ---------------------------------------------------------------------------
// Kernel 4: O = P @ V  (A = split P, K-major; B = split V^T [d][s], K-major)
// ---------------------------------------------------------------------------
__global__ __launch_bounds__(256, 2) void pv_mma(float* __restrict__ out) {
    __shared__ SmemTiles sm;
    const int b = blockIdx.z;
    const int it = blockIdx.y;
    const int m0 = it * 128;
    const int n0 = blockIdx.x * 128;
    const int nch = (it + 1) * 4;       // kend = (it+1)*128, chunks of 32

    float acc[4][4][4];
#pragma unroll
    for (int i = 0; i < 4; i++)
#pragma unroll
        for (int j = 0; j < 4; j++)
#pragma unroll
            for (int r = 0; r < 4; r++) acc[i][j][r] = 0.0f;

    const size_t ao = ((size_t)b * SS + m0) * SS;
    const size_t bo = (size_t)b * DD * SS + (size_t)n0 * SS;
    mma_mainloop(g_p_hi + ao, g_p_lo + ao, g_vT_hi + bo, g_vT_lo + bo,
                 SS, SS, nch, &sm, acc);

    const int lane = threadIdx.x & 31, wid = threadIdx.x >> 5;
    const int wm = wid >> 2, wn = wid & 3;
    const int g = lane >> 2, tg = lane & 3;
    float* C = out + (size_t)b * SS * DD;

#pragma unroll
    for (int fm = 0; fm < 4; fm++)
#pragma unroll
        for (int fn = 0; fn < 4; fn++) {
            const int n = n0 + wn * 32 + fn * 8 + tg * 2;
#pragma unroll
            for (int half = 0; half < 2; half++) {
                const int m = m0 + wm * 64 + fm * 16 + g + half * 8;
                float2 v;
                v.x = acc[fm][fn][half * 2];
                v.y = acc[fm][fn][half * 2 + 1];
                *(float2*)(C + (size_t)m * DD + n) = v;
            }
        }
}

// ---------------------------------------------------------------------------
extern "C" void kernel_launch(void* const* d_in, const int* in_sizes, int n_in,
                              void* d_out, int out_size) {
    const float* x  = (const float*)d_in[0];
    const float* wq = (const float*)d_in[1];
    const float* wk = (const float*)d_in[2];
    const float* wv = (const float*)d_in[3];
    float* out = (float*)d_out;
    (void)in_sizes; (void)n_in; (void)out_size;

    // 0) split inputs into bf16 hi/lo
    split_all<<<dim3(1024, 4), 256>>>(x, wq, wk, wv);

    // 1) Q, K, V^T projections (tensor cores via mma.sync)
    qkv_mma<<<dim3(DD / 128, (BB * SS) / 128, 3), 256>>>();

    // 2) causal scores (lower-triangular tiles only)
    const int ntri = (SS / 128) * (SS / 128 + 1) / 2;   // 136
    scores_mma<<<dim3(ntri, BB), 256>>>();

    // 3) softmax -> split-bf16 P
    softmax_rows<<<dim3(SS, BB), 256>>>();

    // 4) O = P @ V
    pv_mma<<<dim3(DD / 128, SS / 128, BB), 256>>>(out);
}

// round 4
// speedup vs baseline: 2.9540x; 1.2833x over previous
#include <cuda_runtime.h>
#include <cuda_bf16.h>
#include <cstdint>
#include <math.h>

#define BB 4
#define SS 2048
#define DD 1024

#define LDB 80                    // smem row stride in bytes (64B data + 16B pad)
#define TILE_B (128 * LDB)        // 10240 B per 128x32 bf16 tile
#define STAGE_B (4 * TILE_B)      // Ah, Al, Bh, Bl
#define SMEM_BYTES (2 * STAGE_B)  // double buffered = 81920

// ---------------------------------------------------------------------------
// Scratch (__device__ globals; allocation-free rule)
// ---------------------------------------------------------------------------
__device__ __align__(16) __nv_bfloat16 g_x_hi[BB*SS*DD], g_x_lo[BB*SS*DD];
__device__ __align__(16) __nv_bfloat16 g_w_hi[3][DD*DD], g_w_lo[3][DD*DD];
__device__ __align__(16) __nv_bfloat16 g_q_hi[BB*SS*DD], g_q_lo[BB*SS*DD];
__device__ __align__(16) __nv_bfloat16 g_k_hi[BB*SS*DD], g_k_lo[BB*SS*DD];
__device__ __align__(16) __nv_bfloat16 g_vT_hi[BB*DD*SS], g_vT_lo[BB*DD*SS];  // [b][d][s]
__device__ __align__(16) float g_p[(size_t)BB*SS*SS];
__device__ __align__(16) __nv_bfloat16 g_p_hi[BB*SS*SS], g_p_lo[BB*SS*SS];

// ---------------------------------------------------------------------------
// PTX primitives
// ---------------------------------------------------------------------------
__device__ __forceinline__ void mma_bf16(float* d, const uint32_t* a, const uint32_t* b) {
    asm volatile(
        "mma.sync.aligned.m16n8k16.row.col.f32.bf16.bf16.f32 "
        "{%0,%1,%2,%3}, {%4,%5,%6,%7}, {%8,%9}, {%0,%1,%2,%3};"
        : "+f"(d[0]), "+f"(d[1]), "+f"(d[2]), "+f"(d[3])
        : "r"(a[0]), "r"(a[1]), "r"(a[2]), "r"(a[3]), "r"(b[0]), "r"(b[1]));
}
#define LDSM4(r0, r1, r2, r3, addr) \
    asm volatile("ldmatrix.sync.aligned.m8n8.x4.shared.b16 {%0,%1,%2,%3}, [%4];" \
                 : "=r"(r0), "=r"(r1), "=r"(r2), "=r"(r3) : "r"(addr))
#define CP_ASYNC16(dst, src) \
    asm volatile("cp.async.cg.shared.global [%0], [%1], 16;" :: "r"(dst), "l"(src))
#define CP_COMMIT() asm volatile("cp.async.commit_group;" ::: "memory")
#define CP_WAIT1()  asm volatile("cp.async.wait_group 1;" ::: "memory")

// ---------------------------------------------------------------------------
// cp.async one 128x32 bf16 tile (K-major, row stride ld elems) into smem tile
// 128 threads: each thread 4 x 16B
// ---------------------------------------------------------------------------
__device__ __forceinline__ void g2s_tile(uint32_t dst_tile, const __nv_bfloat16* __restrict__ g,
                                         size_t ld, int k0, int tid) {
#pragma unroll
    for (int i = 0; i < 4; i++) {
        int slot = tid + (i << 7);      // 0..511
        int row = slot >> 2;            // 0..127
        int c = slot & 3;               // 16B chunk
        uint32_t dst = dst_tile + row * LDB + c * 16;
        const void* src = g + (size_t)row * ld + k0 + c * 8;
        CP_ASYNC16(dst, src);
    }
}

// ---------------------------------------------------------------------------
// Mainloop: acc[4][8][4] += split3(A[128,K]) . split3(B[128,K])^T
// 128 threads, 4 warps in 2x2 grid, warp tile 64x64.
// Double-buffered cp.async pipeline, ldmatrix fragments.
// ---------------------------------------------------------------------------
__device__ __forceinline__ void mma_mainloop(
    const __nv_bfloat16* __restrict__ Ah, const __nv_bfloat16* __restrict__ Al,
    const __nv_bfloat16* __restrict__ Bh, const __nv_bfloat16* __restrict__ Bl,
    size_t lda, size_t ldb, int nch, uint32_t smem, float acc[4][8][4]) {

    const int tid = threadIdx.x;
    const int lane = tid & 31, wid = tid >> 5;
    const int wm = wid >> 1, wn = wid & 1;

    // ldmatrix per-lane address offsets (within a tile)
    const uint32_t a_off = (uint32_t)(wm * 64 + (lane & 15)) * LDB + ((lane & 16) ? 16u : 0u);
    const uint32_t b_off = (uint32_t)(wn * 64 + (lane & 7) + ((lane & 16) ? 8 : 0)) * LDB
                         + ((lane & 8) ? 16u : 0u);

    // prologue: stage 0
    {
        uint32_t st = smem;
        g2s_tile(st,              Ah, lda, 0, tid);
        g2s_tile(st + TILE_B,     Al, lda, 0, tid);
        g2s_tile(st + 2 * TILE_B, Bh, ldb, 0, tid);
        g2s_tile(st + 3 * TILE_B, Bl, ldb, 0, tid);
        CP_COMMIT();
    }

    for (int c = 0; c < nch; c++) {
        if (c + 1 < nch) {
            uint32_t st = smem + ((c + 1) & 1) * STAGE_B;
            const int k0 = (c + 1) * 32;
            g2s_tile(st,              Ah, lda, k0, tid);
            g2s_tile(st + TILE_B,     Al, lda, k0, tid);
            g2s_tile(st + 2 * TILE_B, Bh, ldb, k0, tid);
            g2s_tile(st + 3 * TILE_B, Bl, ldb, k0, tid);
        }
        CP_COMMIT();
        CP_WAIT1();
        __syncthreads();

        const uint32_t st = smem + (c & 1) * STAGE_B;
#pragma unroll
        for (int ks = 0; ks < 2; ks++) {
            const uint32_t ka = st + a_off + ks * 32;
            const uint32_t kb = st + 2 * TILE_B + b_off + ks * 32;
            uint32_t ah[4][4], bh[8][2], bl[8][2];
#pragma unroll
            for (int fm = 0; fm < 4; fm++)
                LDSM4(ah[fm][0], ah[fm][1], ah[fm][2], ah[fm][3], ka + fm * 16 * LDB);
#pragma unroll
            for (int p = 0; p < 4; p++)
                LDSM4(bh[2*p][0], bh[2*p][1], bh[2*p+1][0], bh[2*p+1][1], kb + p * 16 * LDB);
#pragma unroll
            for (int p = 0; p < 4; p++)
                LDSM4(bl[2*p][0], bl[2*p][1], bl[2*p+1][0], bl[2*p+1][1],
                      kb + TILE_B + p * 16 * LDB);

            // term 1: Ah x Bh
#pragma unroll
            for (int fm = 0; fm < 4; fm++)
#pragma unroll
                for (int fn = 0; fn < 8; fn++) mma_bf16(acc[fm][fn], ah[fm], bh[fn]);
            // term 2: Ah x Bl
#pragma unroll
            for (int fm = 0; fm < 4; fm++)
#pragma unroll
                for (int fn = 0; fn < 8; fn++) mma_bf16(acc[fm][fn], ah[fm], bl[fn]);
            // term 3: Al x Bh (reload into ah regs)
#pragma unroll
            for (int fm = 0; fm < 4; fm++)
                LDSM4(ah[fm][0], ah[fm][1], ah[fm][2], ah[fm][3],
                      ka + TILE_B + fm * 16 * LDB);
#pragma unroll
            for (int fm = 0; fm < 4; fm++)
#pragma unroll
                for (int fn = 0; fn < 8; fn++) mma_bf16(acc[fm][fn], ah[fm], bh[fn]);
        }
        __syncthreads();
    }
}

#define ZERO_ACC(acc) \
    do { _Pragma("unroll") for (int i = 0; i < 4; i++) \
         _Pragma("unroll") for (int j = 0; j < 8; j++) \
         _Pragma("unroll") for (int r = 0; r < 4; r++) (acc)[i][j][r] = 0.0f; } while (0)

// ---------------------------------------------------------------------------
// Kernel 0: split fp32 -> (hi, lo) bf16 for x, Wq, Wk, Wv
// ---------------------------------------------------------------------------
__global__ __launch_bounds__(256) void split_all(
    const float* __restrict__ x, const float* __restrict__ wq,
    const float* __restrict__ wk, const float* __restrict__ wv) {
    const int which = blockIdx.y;
    const float* src = (which == 0) ? x : (which == 1) ? wq : (which == 2) ? wk : wv;
    __nv_bfloat16* hi = (which == 0) ? g_x_hi : g_w_hi[which - 1];
    __nv_bfloat16* lo = (which == 0) ? g_x_lo : g_w_lo[which - 1];
    const int n = (which == 0) ? BB * SS * DD : DD * DD;
    for (int i = blockIdx.x * 256 + threadIdx.x; i < n; i += gridDim.x * 256) {
        float f = src[i];
        __nv_bfloat16 h = __float2bfloat16(f);
        hi[i] = h;
        lo[i] = __float2bfloat16(f - __bfloat162float(h));
    }
}

// ---------------------------------------------------------------------------
// Kernel 1: QKV.  z=0 -> Q(split), z=1 -> K(split), z=2 -> V^T(split)
// ---------------------------------------------------------------------------
__global__ __launch_bounds__(128, 2) void qkv_mma() {
    extern __shared__ char smraw[];
    const uint32_t smem = (uint32_t)__cvta_generic_to_shared(smraw);
    const int z = blockIdx.z;
    const int m0 = blockIdx.y * 128;
    const int n0 = blockIdx.x * 128;

    float acc[4][8][4];
    ZERO_ACC(acc);

    mma_mainloop(g_x_hi + (size_t)m0 * DD, g_x_lo + (size_t)m0 * DD,
                 g_w_hi[z] + (size_t)n0 * DD, g_w_lo[z] + (size_t)n0 * DD,
                 DD, DD, DD / 32, smem, acc);

    const int lane = threadIdx.x & 31, wid = threadIdx.x >> 5;
    const int wm = wid >> 1, wn = wid & 1;
    const int g = lane >> 2, tg = lane & 3;

#pragma unroll
    for (int fm = 0; fm < 4; fm++)
#pragma unroll
        for (int fn = 0; fn < 8; fn++) {
            const int n = n0 + wn * 64 + fn * 8 + tg * 2;
#pragma unroll
            for (int half = 0; half < 2; half++) {
                const int m = m0 + wm * 64 + fm * 16 + g + half * 8;
                float f0 = acc[fm][fn][half * 2], f1 = acc[fm][fn][half * 2 + 1];
                if (z < 2) {
                    __nv_bfloat16* H = z ? g_k_hi : g_q_hi;
                    __nv_bfloat16* L = z ? g_k_lo : g_q_lo;
                    __nv_bfloat16 h0 = __float2bfloat16(f0), h1 = __float2bfloat16(f1);
                    __nv_bfloat162 h2; h2.x = h0; h2.y = h1;
                    __nv_bfloat162 l2;
                    l2.x = __float2bfloat16(f0 - __bfloat162float(h0));
                    l2.y = __float2bfloat16(f1 - __bfloat162float(h1));
                    *(__nv_bfloat162*)(H + (size_t)m * DD + n) = h2;
                    *(__nv_bfloat162*)(L + (size_t)m * DD + n) = l2;
                } else {
                    const int b = m >> 11, ml = m & (SS - 1);
                    const size_t vb = (size_t)b * DD * SS;
                    __nv_bfloat16 h0 = __float2bfloat16(f0), h1 = __float2bfloat16(f1);
                    g_vT_hi[vb + (size_t)n * SS + ml] = h0;
                    g_vT_lo[vb + (size_t)n * SS + ml] = __float2bfloat16(f0 - __bfloat162float(h0));
                    g_vT_hi[vb + (size_t)(n + 1) * SS + ml] = h1;
                    g_vT_lo[vb + (size_t)(n + 1) * SS + ml] = __float2bfloat16(f1 - __bfloat162float(h1));
                }
            }
        }
}

// ---------------------------------------------------------------------------
// Kernel 2: causal scores (lower-triangular 128x128 tiles)
// ---------------------------------------------------------------------------
__global__ __launch_bounds__(128, 2) void scores_mma() {
    extern __shared__ char smraw[];
    const uint32_t smem = (uint32_t)__cvta_generic_to_shared(smraw);
    const int t = blockIdx.x;
    int it = (int)floorf((sqrtf(8.0f * (float)t + 1.0f) - 1.0f) * 0.5f);
    while ((it + 1) * (it + 2) / 2 <= t) ++it;
    while (it * (it + 1) / 2 > t) --it;
    const int jt = t - it * (it + 1) / 2;
    const int b = blockIdx.y;
    const int m0 = it * 128, n0 = jt * 128;

    float acc[4][8][4];
    ZERO_ACC(acc);

    const size_t ao = ((size_t)b * SS + m0) * DD;
    const size_t bo = ((size_t)b * SS + n0) * DD;
    mma_mainloop(g_q_hi + ao, g_q_lo + ao, g_k_hi + bo, g_k_lo + bo,
                 DD, DD, DD / 32, smem, acc);

    const int lane = threadIdx.x & 31, wid = threadIdx.x >> 5;
    const int wm = wid >> 1, wn = wid & 1;
    const int g = lane >> 2, tg = lane & 3;
    float* C = g_p + (size_t)b * SS * SS;
    const float alpha = 1.0f / 32.0f;

#pragma unroll
    for (int fm = 0; fm < 4; fm++)
#pragma unroll
        for (int fn = 0; fn < 8; fn++) {
            const int n = n0 + wn * 64 + fn * 8 + tg * 2;
#pragma unroll
            for (int half = 0; half < 2; half++) {
                const int m = m0 + wm * 64 + fm * 16 + g + half * 8;
                float2 v;
                v.x = acc[fm][fn][half * 2] * alpha;
                v.y = acc[fm][fn][half * 2 + 1] * alpha;
                *(float2*)(C + (size_t)m * SS + n) = v;
            }
        }
}

// ---------------------------------------------------------------------------
// Kernel 3: causal row softmax; emits split-bf16 P, zero-filled to tile edge
// ---------------------------------------------------------------------------
__global__ __launch_bounds__(256) void softmax_rows() {
    const int i = blockIdx.x, b = blockIdx.y;
    const size_t rowoff = ((size_t)b * SS + i) * SS;
    float* row = g_p + rowoff;
    const int len = i + 1;
    const int tid = threadIdx.x, lane = tid & 31, wid = tid >> 5;

    __shared__ float red[8];
    __shared__ float s_max, s_sum;

    float m = -1e30f;
    for (int j = tid; j < len; j += 256) m = fmaxf(m, row[j]);
#pragma unroll
    for (int o = 16; o; o >>= 1) m = fmaxf(m, __shfl_xor_sync(0xffffffffu, m, o));
    if (lane == 0) red[wid] = m;
    __syncthreads();
    if (tid < 32) {
        float v = (tid < 8) ? red[tid] : -1e30f;
#pragma unroll
        for (int o = 4; o; o >>= 1) v = fmaxf(v, __shfl_xor_sync(0xffffffffu, v, o));
        if (tid == 0) s_max = v;
    }
    __syncthreads();
    m = s_max;

    float s = 0.0f;
    for (int j = tid; j < len; j += 256) {
        float e = __expf(row[j] - m);
        row[j] = e;
        s += e;
    }
#pragma unroll
    for (int o = 16; o; o >>= 1) s += __shfl_xor_sync(0xffffffffu, s, o);
    __syncthreads();
    if (lane == 0) red[wid] = s;
    __syncthreads();
    if (tid < 32) {
        float v = (tid < 8) ? red[tid] : 0.0f;
#pragma unroll
        for (int o = 4; o; o >>= 1) v += __shfl_xor_sync(0xffffffffu, v, o);
        if (tid == 0) s_sum = v;
    }
    __syncthreads();
    const float inv = 1.0f / s_sum;

    __nv_bfloat16* ph = g_p_hi + rowoff;
    __nv_bfloat16* pl = g_p_lo + rowoff;
    for (int j = tid; j < len; j += 256) {
        float p = row[j] * inv;
        __nv_bfloat16 h = __float2bfloat16(p);
        ph[j] = h;
        pl[j] = __float2bfloat16(p - __bfloat162float(h));
    }
    const int tend = ((i >> 7) + 1) << 7;
    const __nv_bfloat16 z = __float2bfloat16(0.0f);
    for (int j = len + tid; j < tend; j += 256) { ph[j] = z; pl[j] = z; }
}

// ---------------------------------------------------------------------------
// Kernel 4: O = P @ V  (A = split P, K-major; B = split V^T [d][s], K-major)
// ---------------------------------------------------------------------------
__global__ __launch_bounds__(128, 2) void pv_mma(float* __restrict__ out) {
    extern __shared__ char smraw[];
    const uint32_t smem = (uint32_t)__cvta_generic_to_shared(smraw);
    const int b = blockIdx.z;
    const int it = blockIdx.y;
    const int m0 = it * 128;
    const int n0 = blockIdx.x * 128;
    const int nch = (it + 1) * 4;       // kend = (it+1)*128

    float acc[4][8][4];
    ZERO_ACC(acc);

    const size_t ao = ((size_t)b * SS + m0) * SS;
    const size_t bo = (size_t)b * DD * SS + (size_t)n0 * SS;
    mma_mainloop(g_p_hi + ao, g_p_lo + ao, g_vT_hi + bo, g_vT_lo + bo,
                 SS, SS, nch, smem, acc);

    const int lane = threadIdx.x & 31, wid = threadIdx.x >> 5;
    const int wm = wid >> 1, wn = wid & 1;
    const int g = lane >> 2, tg = lane & 3;
    float* C = out + (size_t)b * SS * DD;

#pragma unroll
    for (int fm = 0; fm < 4; fm++)
#pragma unroll
        for (int fn = 0; fn < 8; fn++) {
            const int n = n0 + wn * 64 + fn * 8 + tg * 2;
#pragma unroll
            for (int half = 0; half < 2; half++) {
                const int m = m0 + wm * 64 + fm * 16 + g + half * 8;
                float2 v;
                v.x = acc[fm][fn][half * 2];
                v.y = acc[fm][fn][half * 2 + 1];
                *(float2*)(C + (size_t)m * DD + n) = v;
            }
        }
}

// ---------------------------------------------------------------------------
extern "C" void kernel_launch(void* const* d_in, const int* in_sizes, int n_in,
                              void* d_out, int out_size) {
    const float* x  = (const float*)d_in[0];
    const float* wq = (const float*)d_in[1];
    const float* wk = (const float*)d_in[2];
    const float* wv = (const float*)d_in[3];
    float* out = (float*)d_out;
    (void)in_sizes; (void)n_in; (void)out_size;

    static bool attr_done = false;
    if (!attr_done) {
        cudaFuncSetAttribute(qkv_mma,    cudaFuncAttributeMaxDynamicSharedMemorySize, SMEM_BYTES);
        cudaFuncSetAttribute(scores_mma, cudaFuncAttributeMaxDynamicSharedMemorySize, SMEM_BYTES);
        cudaFuncSetAttribute(pv_mma,     cudaFuncAttributeMaxDynamicSharedMemorySize, SMEM_BYTES);
        attr_done = true;
    }

    // 0) split inputs into bf16 hi/lo
    split_all<<<dim3(1024, 4), 256>>>(x, wq, wk, wv);

    // 1) Q, K, V^T projections
    qkv_mma<<<dim3(DD / 128, (BB * SS) / 128, 3), 128, SMEM_BYTES>>>();

    // 2) causal scores (lower-triangular tiles only)
    const int ntri = (SS / 128) * (SS / 128 + 1) / 2;   // 136
    scores_mma<<<dim3(ntri, BB), 128, SMEM_BYTES>>>();

    // 3) softmax -> split-bf16 P
    softmax_rows<<<dim3(SS, BB), 256>>>();

    // 4) O = P @ V
    pv_mma<<<dim3(DD / 128, SS / 128, BB), 128, SMEM_BYTES>>>(out);
}